// round 16
// baseline (speedup 1.0000x reference)
#include <cuda_runtime.h>
#include <cstdint>

// GradientLayer jet-propagation via legacy mma.sync bf16 (sm_80 PTX -> runs on
// Blackwell tensor cores; tcgen05 is blocked by the compute_103 virtual arch).
// M=128 rows/CTA = 16 samples x 8 jet channels. 3-product hi/lo bf16 split.
// R16: prep kernel pre-splits W into fragment-major 16B units in __device__
// scratch; hot loop stages via cp.async (3-buffer, 1 barrier/chunk); state in
// fragment-major smem so A=LDS.128x4, B=LDS.128x8 per 48 MMAs per chunk.

#define HD   256
#define SPC  16
#define NCHK 16            // 16 k-chunks of 16
#define CHB  16384u        // staged W chunk bytes (hi/lo interleaved units)
#define ROWB 1088u         // state row stride bytes (1024 data + 64 pad)
#define OFF_B 0u
#define OFF_S 49152u       // 3 * CHB
#define SMEM_BYTES (49152 + 128 * 1088)   // 188416

__device__ __align__(16) unsigned char g_wpk[3u * 16u * 16384u];

__device__ __forceinline__ uint32_t bf2(float lo, float hi) {
    uint32_t r;
    asm("cvt.rn.bf16x2.f32 %0, %1, %2;" : "=r"(r) : "f"(hi), "f"(lo));
    return r;
}
__device__ __forceinline__ float bflo(uint32_t p) { return __uint_as_float(p << 16); }
__device__ __forceinline__ float bfhi(uint32_t p) { return __uint_as_float(p & 0xffff0000u); }

__device__ __forceinline__ void split2(float f0, float f1, uint32_t& ph, uint32_t& pl) {
    ph = bf2(f0, f1);
    pl = bf2(f0 - bflo(ph), f1 - bfhi(ph));
}

__device__ __forceinline__ void mma16816(float* d, uint32_t a0, uint32_t a1,
                                         uint32_t a2, uint32_t a3,
                                         uint32_t b0, uint32_t b1) {
    asm volatile(
        "mma.sync.aligned.m16n8k16.row.col.f32.bf16.bf16.f32 "
        "{%0,%1,%2,%3}, {%4,%5,%6,%7}, {%8,%9}, {%0,%1,%2,%3};"
        : "+f"(d[0]), "+f"(d[1]), "+f"(d[2]), "+f"(d[3])
        : "r"(a0), "r"(a1), "r"(a2), "r"(a3), "r"(b0), "r"(b1));
}

__device__ __forceinline__ uint32_t s2u(const void* p) {
    uint32_t a;
    asm("{.reg .u64 t; cvta.to.shared.u64 t, %1; cvt.u32.u64 %0, t;}" : "=r"(a) : "l"(p));
    return a;
}
#define CPASYNC16(d, s) asm volatile("cp.async.cg.shared.global [%0], [%1], 16;" :: "r"(d), "l"(s))
#define CPCOMMIT() asm volatile("cp.async.commit_group;" ::: "memory")
#define CPWAIT1()  asm volatile("cp.async.wait_group 1;" ::: "memory")
#define CPWAIT0()  asm volatile("cp.async.wait_group 0;" ::: "memory")

// ---- prep: pre-split W1..W3 into fragment-major hi/lo bf16 units ----
// unit u (16B) at [l][t][n][u] = {hi pair(u), hi pair(u+4), lo pair(u), lo pair(u+4)},
// pair p covers k = t*16 + 2p, 2p+1 of column n.
__global__ void prep_kernel(const float* __restrict__ W1,
                            const float* __restrict__ W2,
                            const float* __restrict__ W3)
{
    const int idx = blockIdx.x * 256 + threadIdx.x;    // 0..12287
    const int l = idx >> 12;
    const int t = (idx >> 8) & 15;
    const int n = idx & 255;
    const float* W = (l == 0) ? W1 : (l == 1) ? W2 : W3;
    float f[16];
    #pragma unroll
    for (int k = 0; k < 16; k++) f[k] = __ldg(W + (t * 16 + k) * HD + n);
    uint32_t ph[8], pl[8];
    #pragma unroll
    for (int p = 0; p < 8; p++) split2(f[2 * p], f[2 * p + 1], ph[p], pl[p]);
    uint4* dst = (uint4*)(g_wpk + (uint32_t)(l * 16 + t) * CHB + (uint32_t)n * 64u);
    #pragma unroll
    for (int u = 0; u < 4; u++)
        dst[u] = make_uint4(ph[u], ph[u + 4], pl[u], pl[u + 4]);
}

__global__ void __launch_bounds__(512, 1)
jet_mma_kernel(const float* __restrict__ x,
               const float* __restrict__ W0, const float* __restrict__ b0,
               const float* __restrict__ b1, const float* __restrict__ b2,
               const float* __restrict__ b3,
               const float* __restrict__ Wo, const float* __restrict__ bo,
               float* __restrict__ out, int B)
{
    extern __shared__ __align__(16) char sm[];
    const uint32_t sb = s2u(sm);
    const int tid  = threadIdx.x;
    const int lane = tid & 31;
    const int w    = tid >> 5;
    const int warpM = w >> 2;
    const int warpN = w & 3;
    const int s0   = blockIdx.x * SPC;

    // stage chunk t of layer l into buffer buf (flat 16KB cp.async memcpy)
    auto stage = [&](int buf, int l, int t) {
        const uint32_t dst = sb + OFF_B + (uint32_t)buf * CHB + (uint32_t)tid * 16u;
        const unsigned char* src = g_wpk + (uint32_t)(l * 16 + t) * CHB + (uint32_t)tid * 16u;
        CPASYNC16(dst, src);
        CPASYNC16(dst + 8192u, src + 8192u);
        CPCOMMIT();
    };

    stage(0, 0, 0);
    stage(1, 0, 1);

    // ---- layer 0: 4->256, write initial jet state (fragment-major units) ----
    {
        const int r  = tid >> 2;              // row 0..127
        const int q  = tid & 3;               // pair quarter
        const int s  = r >> 3, ch = r & 7;
        const int gs = s0 + s;
        float x0 = 0.f, x1 = 0.f, x2 = 0.f, x3 = 0.f;
        if (gs < B) {
            x0 = __ldg(x + gs * 4 + 0); x1 = __ldg(x + gs * 4 + 1);
            x2 = __ldg(x + gs * 4 + 2); x3 = __ldg(x + gs * 4 + 3);
        }
        char* rowp = sm + OFF_S + (uint32_t)r * ROWB;
        #pragma unroll 4
        for (int pi = 0; pi < 32; pi++) {
            const int p = q * 32 + pi;        // global pair 0..127
            float o[2];
            #pragma unroll
            for (int e = 0; e < 2; e++) {
                const int j = 2 * p + e;
                float w0v = __ldg(W0 + j),          w1v = __ldg(W0 + HD + j);
                float w2v = __ldg(W0 + 2 * HD + j), w3v = __ldg(W0 + 3 * HD + j);
                float u = __ldg(b0 + j) + x0 * w0v + x1 * w1v + x2 * w2v + x3 * w3v;
                float v = tanhf(u);
                float d = 1.f - v * v;
                float m = -2.f * v * d;
                float wg = (ch == 1 || ch == 5) ? w0v : (ch == 2 || ch == 6) ? w1v
                         : (ch == 3 || ch == 7) ? w2v : w3v;
                o[e] = (ch == 0) ? v : (ch <= 4) ? d * wg : m * wg * wg;
            }
            uint32_t ph, pl;
            split2(o[0], o[1], ph, pl);
            const int c = p >> 3, loc = p & 7, u = loc & 3, slot = loc >> 2;
            char* base = rowp + c * 64 + u * 16 + slot * 4;
            *(uint32_t*)(base)     = ph;
            *(uint32_t*)(base + 8) = pl;
        }
    }
    __syncthreads();

    // ---- hidden layers ----
    const float* bl[3] = { b1, b2, b3 };

    #pragma unroll 1
    for (int layer = 0; layer < 3; layer++) {
        float acc[2][8][4];
        #pragma unroll
        for (int mt = 0; mt < 2; mt++)
            #pragma unroll
            for (int nt = 0; nt < 8; nt++)
                #pragma unroll
                for (int q = 0; q < 4; q++) acc[mt][nt][q] = 0.f;

        #pragma unroll 1
        for (int t = 0; t < NCHK; t++) {
            if (t == NCHK - 1) { CPWAIT0(); } else { CPWAIT1(); }
            __syncthreads();
            if (t + 2 < NCHK) stage((t + 2) % 3, layer, t + 2);

            const char* bbase = sm + OFF_B + (uint32_t)(t % 3) * CHB;
            uint4 A0[2], A1[2];
            #pragma unroll
            for (int mt = 0; mt < 2; mt++) {
                const uint32_t r0 = (uint32_t)(warpM * 32 + mt * 16 + (lane >> 2));
                const char* ap = sm + OFF_S + r0 * ROWB + t * 64 + (lane & 3) * 16;
                A0[mt] = *(const uint4*)(ap);
                A1[mt] = *(const uint4*)(ap + 8 * ROWB);
            }
            #pragma unroll
            for (int nt = 0; nt < 8; nt++) {
                const uint32_t nB = (uint32_t)(warpN * 64 + nt * 8 + (lane >> 2));
                uint4 Bv = *(const uint4*)(bbase + nB * 64u + (lane & 3) * 16);
                #pragma unroll
                for (int mt = 0; mt < 2; mt++) {
                    mma16816(acc[mt][nt], A0[mt].x, A1[mt].x, A0[mt].y, A1[mt].y, Bv.x, Bv.y);
                    mma16816(acc[mt][nt], A0[mt].x, A1[mt].x, A0[mt].y, A1[mt].y, Bv.z, Bv.w);
                    mma16816(acc[mt][nt], A0[mt].z, A1[mt].z, A0[mt].w, A1[mt].w, Bv.x, Bv.y);
                }
            }
        }
        __syncthreads();          // all reads of state/B done
        if (layer < 2) { stage(0, layer + 1, 0); stage(1, layer + 1, 1); }

        // ---- tanh-jet epilogue: acc -> new state ----
        const float* bp = bl[layer];
        const int srcU = lane & 3;            // channel-0 row lane
        const int srcG = (lane - 16) & 31;    // gradient-channel source lane
        const int ch   = lane >> 2;
        #pragma unroll
        for (int mt = 0; mt < 2; mt++) {
            #pragma unroll
            for (int nt = 0; nt < 8; nt++) {
                float* a = acc[mt][nt];
                const int jp = warpN * 32 + nt * 4 + (lane & 3);   // pair index
                const int jc = 2 * jp;
                const float bj0 = __ldg(bp + jc);
                const float bj1 = __ldg(bp + jc + 1);
                const int c = jp >> 3, loc = jp & 7, u = loc & 3, slot = loc >> 2;
                #pragma unroll
                for (int grp = 0; grp < 2; grp++) {
                    const float va = a[grp * 2], vb = a[grp * 2 + 1];
                    const float ua = __shfl_sync(0xffffffffu, va, srcU);
                    const float ub = __shfl_sync(0xffffffffu, vb, srcU);
                    const float ga = __shfl_sync(0xffffffffu, va, srcG);
                    const float gb = __shfl_sync(0xffffffffu, vb, srcG);
                    const float ta = tanhf(ua + bj0);
                    const float tb = tanhf(ub + bj1);
                    const float da = 1.f - ta * ta, db = 1.f - tb * tb;
                    const float ma = -2.f * ta * da, mb = -2.f * tb * db;
                    const float oa = (ch == 0) ? ta : (ch <= 4) ? da * va
                                    : da * va + ma * ga * ga;
                    const float ob = (ch == 0) ? tb : (ch <= 4) ? db * vb
                                    : db * vb + mb * gb * gb;
                    uint32_t ph, pl;
                    split2(oa, ob, ph, pl);
                    const uint32_t r = (uint32_t)(warpM * 32 + mt * 16 + (lane >> 2) + grp * 8);
                    char* base = sm + OFF_S + r * ROWB + c * 64 + u * 16 + slot * 4;
                    *(uint32_t*)(base)     = ph;
                    *(uint32_t*)(base + 8) = pl;
                }
            }
        }
        __syncthreads();
    }

    // ---- output layer 256->2 + divergence: warp w handles sample w ----
    {
        const int s  = w;
        const int gs = s0 + s;
        float p0[8], p1[8];
        #pragma unroll
        for (int c = 0; c < 8; c++) { p0[c] = 0.f; p1[c] = 0.f; }
        #pragma unroll
        for (int it = 0; it < 4; it++) {
            const int jp = it * 32 + lane;
            const int j  = 2 * jp;
            const int c = jp >> 3, loc = jp & 7, u = loc & 3, slot = loc >> 2;
            const float wo00 = __ldg(Wo + j * 2 + 0);
            const float wo01 = __ldg(Wo + j * 2 + 1);
            const float wo10 = __ldg(Wo + (j + 1) * 2 + 0);
            const float wo11 = __ldg(Wo + (j + 1) * 2 + 1);
            #pragma unroll
            for (int ch = 0; ch < 8; ch++) {
                const uint32_t r = (uint32_t)(s * 8 + ch);
                const char* base = sm + OFF_S + r * ROWB + c * 64 + u * 16 + slot * 4;
                uint32_t uh = *(const uint32_t*)(base);
                uint32_t ul = *(const uint32_t*)(base + 8);
                float v0 = bflo(uh) + bflo(ul);
                float v1 = bfhi(uh) + bfhi(ul);
                p0[ch] = fmaf(v0, wo00, fmaf(v1, wo10, p0[ch]));
                p1[ch] = fmaf(v0, wo01, fmaf(v1, wo11, p1[ch]));
            }
        }
        #pragma unroll
        for (int off = 16; off > 0; off >>= 1) {
            #pragma unroll
            for (int c = 0; c < 8; c++) {
                p0[c] += __shfl_xor_sync(0xffffffffu, p0[c], off);
                p1[c] += __shfl_xor_sync(0xffffffffu, p1[c], off);
            }
        }
        if (lane == 0 && gs < B) {
            float cc  = p0[0] + __ldg(bo + 0);
            float Fi  = p1[0] + __ldg(bo + 1);
            float ct  = p0[4];
            float cg0 = p0[1], cg1 = p0[2], cg2 = p0[3];
            float fg0 = p1[1], fg1 = p1[2], fg2 = p1[3];
            float clap = p0[5] + p0[6] + p0[7];
            float flap = p1[5] + p1[6] + p1[7];
            float jdiv = -clap
                       - (cg0 * fg0 + cg1 * fg1 + cg2 * fg2 + cc * flap)
                       + 0.1f * (cg0 + cg1 + cg2);
            out[gs]                 = cc;
            out[B + gs]             = ct;
            out[2 * B + gs * 3 + 0] = cg0;
            out[2 * B + gs * 3 + 1] = cg1;
            out[2 * B + gs * 3 + 2] = cg2;
            out[5 * B + gs]         = Fi;
            out[6 * B + gs * 3 + 0] = fg0;
            out[6 * B + gs * 3 + 1] = fg1;
            out[6 * B + gs * 3 + 2] = fg2;
            out[9 * B + gs]         = flap;
            out[10 * B + gs]        = jdiv;
        }
    }
}

extern "C" void kernel_launch(void* const* d_in, const int* in_sizes, int n_in,
                              void* d_out, int out_size)
{
    const float* x  = (const float*)d_in[0];
    const float* W0 = (const float*)d_in[1];
    const float* b0 = (const float*)d_in[2];
    const float* W1 = (const float*)d_in[3];
    const float* b1 = (const float*)d_in[4];
    const float* W2 = (const float*)d_in[5];
    const float* b2 = (const float*)d_in[6];
    const float* W3 = (const float*)d_in[7];
    const float* b3 = (const float*)d_in[8];
    const float* Wo = (const float*)d_in[9];
    const float* bo = (const float*)d_in[10];
    float* out = (float*)d_out;

    const int B = in_sizes[0] / 4;

    prep_kernel<<<48, 256>>>(W1, W2, W3);

    cudaFuncSetAttribute(jet_mma_kernel,
                         cudaFuncAttributeMaxDynamicSharedMemorySize, SMEM_BYTES);
    dim3 grid((B + SPC - 1) / SPC);
    jet_mma_kernel<<<grid, 512, SMEM_BYTES>>>(x, W0, b0, b1, b2, b3,
                                              Wo, bo, out, B);
}